// round 1
// baseline (speedup 1.0000x reference)
#include <cuda_runtime.h>
#include <cuda_bf16.h>
#include <stdint.h>

#define Gx 106
#define G2x (106 * 106)
#define G3x (106 * 106 * 106)
#define MAXB 2
#define CROP 100
#define CROPV (100 * 100 * 100)

// Interleaved scratch: per cell (grid_sum, acc_sum). Size = B * G^3 float2.
__device__ float g_combo[2 * MAXB * G3x];

// ---------------------------------------------------------------------------
// Zero the scratch (float4 stores; count divides exactly).
// ---------------------------------------------------------------------------
__global__ void splat_zero_kernel(int n4) {
    int i = blockIdx.x * blockDim.x + threadIdx.x;
    if (i < n4) {
        reinterpret_cast<float4*>(g_combo)[i] = make_float4(0.f, 0.f, 0.f, 0.f);
    }
}

// ---------------------------------------------------------------------------
// Scatter: one thread per point. 4x4x4 window, red.global.add.v2.f32 per cell.
// ---------------------------------------------------------------------------
__global__ void splat_scatter_kernel(const float* __restrict__ points,
                                     const float* __restrict__ dens,
                                     const float* __restrict__ bbox,
                                     int total, int Npb) {
    int t = blockIdx.x * blockDim.x + threadIdx.x;
    if (t >= total) return;

    int b = t / Npb;
    float d = dens[t];

    float px = points[3 * t + 0];
    float py = points[3 * t + 1];
    float pz = points[3 * t + 2];

    int lo[3];
    float w[3][4];

    // Grid axis a uses point coordinate (2 - a) and bbox row (2 - a)
    // (the reference reverses the last dim of both points and bbox).
#pragma unroll
    for (int a = 0; a < 3; a++) {
        float c = (a == 0) ? pz : ((a == 1) ? py : px);
        int bd = 2 - a;
        // bbox layout: (1,3,2) row-major -> bbox[bd*2 + {0,1}]
        float blo  = __fsub_rn(bbox[bd * 2 + 0], 0.03f);   // pad = (KR+1)*CELL
        float bhi  = __fadd_rn(bbox[bd * 2 + 1], 0.03f);
        float span = __fsub_rn(bhi, blo);
        // pg = ((c - blo) - CELL/2) / span * G   (op-for-op, IEEE rn)
        float tt = __fsub_rn(__fsub_rn(c, blo), 0.005f);
        float pg = __fmul_rn(__fdiv_rn(tt, span), 106.0f);
        float pgr = rintf(pg);           // round-half-even == jnp.round
        int   gi  = (int)pgr;
        float frac = pg - pgr;           // Sterbenz-exact

        // Only one of offsets -2/+2 is nonzero -> 4-wide window.
        int l = (frac < 0.0f) ? -2 : -1;
        lo[a] = gi + l;
#pragma unroll
        for (int o = 0; o < 4; o++) {
            float dd = (float)(l + o) - frac;            // exact
            w[a][o] = fmaxf(1.0f - fabsf(dd) * 0.5f, 0.0f);
        }
    }

    int cell_base = b * G3x + lo[0] * G2x + lo[1] * Gx + lo[2];

#pragma unroll
    for (int i = 0; i < 4; i++) {
        float w0 = w[0][i];
#pragma unroll
        for (int j = 0; j < 4; j++) {
            float wij  = w0 * w[1][j];
            float wijd = wij * d;
            int cb = cell_base + i * G2x + j * Gx;
#pragma unroll
            for (int k = 0; k < 4; k++) {
                float wk = w[2][k];
                float wv = wij * wk;    // weight -> acc
                float gv = wijd * wk;   // weight*density -> grid
                float* addr = g_combo + 2 * (cb + k);
                asm volatile("red.global.add.v2.f32 [%0], {%1, %2};"
                             :: "l"(addr), "f"(gv), "f"(wv)
                             : "memory");
            }
        }
    }
}

// ---------------------------------------------------------------------------
// Normalize + crop [3 : G-3] and write output: grid block, then acc block.
// ---------------------------------------------------------------------------
__global__ void splat_finalize_kernel(float* __restrict__ out,
                                      int B, int writeAcc) {
    int o = blockIdx.x * blockDim.x + threadIdx.x;
    int tot = B * CROPV;
    if (o >= tot) return;
    int b = o / CROPV;
    int r = o - b * CROPV;
    int i = r / (CROP * CROP);
    int rem = r - i * (CROP * CROP);
    int j = rem / CROP;
    int k = rem - j * CROP;

    int src = b * G3x + (i + 3) * G2x + (j + 3) * Gx + (k + 3);
    float2 ga = reinterpret_cast<const float2*>(g_combo)[src];
    float gv = ga.x;
    float av = ga.y;
    float outg = (av > 0.0f) ? (gv / (av + 1e-9f)) : gv;
    out[o] = outg;
    if (writeAcc) out[tot + o] = av;
}

// ---------------------------------------------------------------------------
extern "C" void kernel_launch(void* const* d_in, const int* in_sizes, int n_in,
                              void* d_out, int out_size) {
    const float* points = (const float*)d_in[0];
    const float* dens   = (const float*)d_in[1];
    const float* bbox   = (const float*)d_in[2];
    float* out = (float*)d_out;

    int total = in_sizes[1];              // B * N
    int B = total / 131072;               // fixed-shape problem: N = 131072
    if (B < 1) B = 1;
    if (B > MAXB) B = MAXB;
    int Npb = total / B;

    int writeAcc = (out_size >= 2 * B * CROPV) ? 1 : 0;

    // 1) zero scratch
    {
        int n4 = (2 * B * G3x) / 4;
        int tpb = 256;
        splat_zero_kernel<<<(n4 + tpb - 1) / tpb, tpb>>>(n4);
    }
    // 2) scatter
    {
        int tpb = 256;
        splat_scatter_kernel<<<(total + tpb - 1) / tpb, tpb>>>(points, dens, bbox,
                                                               total, Npb);
    }
    // 3) normalize + crop + write
    {
        int tot = B * CROPV;
        int tpb = 256;
        splat_finalize_kernel<<<(tot + tpb - 1) / tpb, tpb>>>(out, B, writeAcc);
    }
}

// round 2
// speedup vs baseline: 1.6286x; 1.6286x over previous
#include <cuda_runtime.h>
#include <cuda_bf16.h>
#include <stdint.h>

#define Gx 106
#define G2x (106 * 106)
#define G3x (106 * 106 * 106)
#define MAXB 2
#define CROP 100
#define CROPV (100 * 100 * 100)

// Interleaved scratch: per cell (grid_sum, acc_sum). Size = B * G^3 float2.
__device__ float g_combo[2 * MAXB * G3x];

// ---------------------------------------------------------------------------
// Zero the scratch (float4 stores; count divides exactly).
// ---------------------------------------------------------------------------
__global__ void splat_zero_kernel(int n4) {
    int i = blockIdx.x * blockDim.x + threadIdx.x;
    if (i < n4) {
        reinterpret_cast<float4*>(g_combo)[i] = make_float4(0.f, 0.f, 0.f, 0.f);
    }
}

// ---------------------------------------------------------------------------
// Scatter: one thread per point. 4x4x4 window.
// Interleaved (grid,acc) layout => one red.v4 covers TWO adjacent k-cells.
// Parity-align the k window to 16B; predicated v2 tail for odd starts.
// ---------------------------------------------------------------------------
__global__ void __launch_bounds__(256)
splat_scatter_kernel(const float* __restrict__ points,
                     const float* __restrict__ dens,
                     const float* __restrict__ bbox,
                     int total, int Npb) {
    int t = blockIdx.x * blockDim.x + threadIdx.x;
    if (t >= total) return;

    int b = t / Npb;
    float d = dens[t];

    float px = points[3 * t + 0];
    float py = points[3 * t + 1];
    float pz = points[3 * t + 2];

    int lo[3];
    float w[3][4];

    // Grid axis a uses point coordinate (2 - a) and bbox row (2 - a)
    // (the reference reverses the last dim of both points and bbox).
#pragma unroll
    for (int a = 0; a < 3; a++) {
        float c = (a == 0) ? pz : ((a == 1) ? py : px);
        int bd = 2 - a;
        float blo  = __fsub_rn(bbox[bd * 2 + 0], 0.03f);   // pad = (KR+1)*CELL
        float bhi  = __fadd_rn(bbox[bd * 2 + 1], 0.03f);
        float span = __fsub_rn(bhi, blo);
        // pg = ((c - blo) - CELL/2) / span * G   (op-for-op, IEEE rn)
        float tt = __fsub_rn(__fsub_rn(c, blo), 0.005f);
        float pg = __fmul_rn(__fdiv_rn(tt, span), 106.0f);
        float pgr = rintf(pg);           // round-half-even == jnp.round
        int   gi  = (int)pgr;
        float frac = pg - pgr;           // Sterbenz-exact

        // Only one of offsets -2/+2 is nonzero -> 4-wide window.
        int l = (frac < 0.0f) ? -2 : -1;
        lo[a] = gi + l;
#pragma unroll
        for (int o = 0; o < 4; o++) {
            float dd = (float)(l + o) - frac;            // exact
            w[a][o] = fmaxf(1.0f - fabsf(dd) * 0.5f, 0.0f);
        }
    }

    // k-axis: align window start to even cell index for 16B v4 atomics.
    int k0 = lo[2];
    int sh = k0 & 1;            // 0: window already aligned; 1: shifted by one
    int ke = k0 - sh;           // even
    float wa = sh ? 0.0f    : w[2][0];
    float wb = sh ? w[2][0] : w[2][1];
    float wc = sh ? w[2][1] : w[2][2];
    float wd = sh ? w[2][2] : w[2][3];
    float we = sh ? w[2][3] : 0.0f;     // tail cell (only when sh==1)

    // cb0 even (G, G^2, G^3, ke all even) => float2 index even => 16B aligned.
    int cb0 = b * G3x + lo[0] * G2x + lo[1] * Gx + ke;

#pragma unroll
    for (int i = 0; i < 4; i++) {
        float w0 = w[0][i];
#pragma unroll
        for (int j = 0; j < 4; j++) {
            float wij  = w0 * w[1][j];
            float wijd = wij * d;
            float* base = g_combo + 2 * (cb0 + i * G2x + j * Gx);

            // cells ke, ke+1
            asm volatile("red.global.add.v4.f32 [%0], {%1, %2, %3, %4};"
                         :: "l"(base),
                            "f"(wijd * wa), "f"(wij * wa),
                            "f"(wijd * wb), "f"(wij * wb)
                         : "memory");
            // cells ke+2, ke+3
            asm volatile("red.global.add.v4.f32 [%0], {%1, %2, %3, %4};"
                         :: "l"(base + 4),
                            "f"(wijd * wc), "f"(wij * wc),
                            "f"(wijd * wd), "f"(wij * wd)
                         : "memory");
            // cell ke+4, predicated (no divergence) — only when sh==1
            asm volatile("{\n\t"
                         ".reg .pred p;\n\t"
                         "setp.ne.s32 p, %3, 0;\n\t"
                         "@p red.global.add.v2.f32 [%0], {%1, %2};\n\t"
                         "}"
                         :: "l"(base + 8), "f"(wijd * we), "f"(wij * we),
                            "r"(sh)
                         : "memory");
        }
    }
}

// ---------------------------------------------------------------------------
// Normalize + crop [3 : G-3] and write output: grid block, then acc block.
// 4 k-cells per thread (CROP divisible by 4 -> float4-aligned output rows).
// ---------------------------------------------------------------------------
__global__ void splat_finalize_kernel(float* __restrict__ out,
                                      int B, int writeAcc) {
    int q = blockIdx.x * blockDim.x + threadIdx.x;
    int tot = B * CROPV;
    int tot4 = tot >> 2;
    if (q >= tot4) return;
    int o = q << 2;
    int b = o / CROPV;
    int r = o - b * CROPV;
    int i = r / (CROP * CROP);
    int rem = r - i * (CROP * CROP);
    int j = rem / CROP;
    int k = rem - j * CROP;           // multiple of 4

    const float2* src = reinterpret_cast<const float2*>(g_combo)
                        + b * G3x + (i + 3) * G2x + (j + 3) * Gx + (k + 3);

    float4 go, ao;
    {
        float2 c0 = __ldg(src + 0);
        float2 c1 = __ldg(src + 1);
        float2 c2 = __ldg(src + 2);
        float2 c3 = __ldg(src + 3);
        go.x = (c0.y > 0.0f) ? (c0.x / (c0.y + 1e-9f)) : c0.x;
        go.y = (c1.y > 0.0f) ? (c1.x / (c1.y + 1e-9f)) : c1.x;
        go.z = (c2.y > 0.0f) ? (c2.x / (c2.y + 1e-9f)) : c2.x;
        go.w = (c3.y > 0.0f) ? (c3.x / (c3.y + 1e-9f)) : c3.x;
        ao = make_float4(c0.y, c1.y, c2.y, c3.y);
    }
    *reinterpret_cast<float4*>(out + o) = go;
    if (writeAcc) *reinterpret_cast<float4*>(out + tot + o) = ao;
}

// ---------------------------------------------------------------------------
extern "C" void kernel_launch(void* const* d_in, const int* in_sizes, int n_in,
                              void* d_out, int out_size) {
    const float* points = (const float*)d_in[0];
    const float* dens   = (const float*)d_in[1];
    const float* bbox   = (const float*)d_in[2];
    float* out = (float*)d_out;

    int total = in_sizes[1];              // B * N
    int B = total / 131072;               // fixed-shape problem: N = 131072
    if (B < 1) B = 1;
    if (B > MAXB) B = MAXB;
    int Npb = total / B;

    int writeAcc = (out_size >= 2 * B * CROPV) ? 1 : 0;

    // 1) zero scratch
    {
        int n4 = (2 * B * G3x) / 4;
        int tpb = 256;
        splat_zero_kernel<<<(n4 + tpb - 1) / tpb, tpb>>>(n4);
    }
    // 2) scatter
    {
        int tpb = 256;
        splat_scatter_kernel<<<(total + tpb - 1) / tpb, tpb>>>(points, dens, bbox,
                                                               total, Npb);
    }
    // 3) normalize + crop + write
    {
        int tot4 = (B * CROPV) >> 2;
        int tpb = 256;
        splat_finalize_kernel<<<(tot4 + tpb - 1) / tpb, tpb>>>(out, B, writeAcc);
    }
}